// round 16
// baseline (speedup 1.0000x reference)
#include <cuda_runtime.h>
#include <cuda_fp16.h>
#include <cstdint>

#define D 64
#define MAXN 100000
#define MAXE 1600000
#define SCAN_BLK 1024

// Scratch (device globals — no allocation allowed)
__device__ float    g_agg[MAXN * D];     // gemm2 output (t2, fp32 for k_final)
__device__ float    g_stats[256];        // sum1, sq1, sum2, sq2
__device__ uint2    g_xh[MAXN * 16];     // x staged fp16 (gather source)
__device__ uint4    g_t1h[MAXN * 8];     // t1 (gemm1 out), packed fp16 rows
__device__ unsigned g_w1h[32 * 64];      // W1 fp16 [k2][n] half2(k-pair)
__device__ unsigned g_w2h[32 * 64];      // W2 fp16 [k2][n]
__device__ int      g_cnt[MAXN + SCAN_BLK];
__device__ int      g_start[MAXN + 1];
__device__ int      g_epos[MAXE];        // per-edge within-dst rank
__device__ int      g_srcs[MAXE];
__device__ int      g_bsum[SCAN_BLK];
__device__ int      g_ctr, g_ctr2;

// ---------------------------------------------------------------------------
// K_prep: stage x fp16 + degree hist (record per-edge rank) + zero stats
//         + W1/W2 -> fp16 [k2][n]
// ---------------------------------------------------------------------------
__global__ __launch_bounds__(256) void k_prep(const float* __restrict__ x,
                                              const int* __restrict__ ei,
                                              const float* __restrict__ W1,
                                              const float* __restrict__ W2,
                                              int N, int E) {
    int i = blockIdx.x * 256 + threadIdx.x;
    if (i < 256) g_stats[i] = 0.f;
    if (i == 0) g_start[N] = E;
    if (i < 2048) {
        int k2 = i >> 6, n = i & 63;
        __half2 h = __floats2half2_rn(W1[(2 * k2) * 64 + n], W1[(2 * k2 + 1) * 64 + n]);
        g_w1h[k2 * 64 + n] = *(unsigned*)&h;
    } else if (i < 4096) {
        int j = i - 2048;
        int k2 = j >> 6, n = j & 63;
        __half2 h = __floats2half2_rn(W2[(2 * k2) * 64 + n], W2[(2 * k2 + 1) * 64 + n]);
        g_w2h[k2 * 64 + n] = *(unsigned*)&h;
    }
    if (i < E) g_epos[i] = atomicAdd(&g_cnt[ei[E + i]], 1);
    int n4 = N * 16;
    if (i >= n4) return;
    float4 v = ((const float4*)x)[i];
    __half2 h0 = __floats2half2_rn(v.x, v.y);
    __half2 h1 = __floats2half2_rn(v.z, v.w);
    uint2 u;
    u.x = *(unsigned*)&h0;
    u.y = *(unsigned*)&h1;
    g_xh[i] = u;
}

__device__ __forceinline__ int block_scan_1024(int v, int* warpsum, int* total) {
    int lane = threadIdx.x & 31, wid = threadIdx.x >> 5;
    int inc = v;
    #pragma unroll
    for (int o = 1; o < 32; o <<= 1) {
        int u = __shfl_up_sync(0xFFFFFFFFu, inc, o);
        if (lane >= o) inc += u;
    }
    if (lane == 31) warpsum[wid] = inc;
    __syncthreads();
    if (wid == 0) {
        int w = warpsum[lane];
        #pragma unroll
        for (int o = 1; o < 32; o <<= 1) {
            int u = __shfl_up_sync(0xFFFFFFFFu, w, o);
            if (lane >= o) w += u;
        }
        warpsum[lane] = w;
    }
    __syncthreads();
    int base = (wid > 0) ? warpsum[wid - 1] : 0;
    *total = warpsum[31];
    return inc + base;
}

// K_scan: single-kernel exclusive scan (resident grid, verified)
__global__ __launch_bounds__(SCAN_BLK) void k_scan(int N) {
    __shared__ int warpsum[32];
    __shared__ int s_base;
    int gi = blockIdx.x * SCAN_BLK + threadIdx.x;
    int v = (gi < N) ? g_cnt[gi] : 0;
    if (gi < N) g_cnt[gi] = 0;
    int total;
    int incl = block_scan_1024(v, warpsum, &total);

    if (threadIdx.x == 0) {
        g_bsum[blockIdx.x] = total;
        __threadfence();
        atomicAdd(&g_ctr, 1);
        while (atomicAdd(&g_ctr, 0) < (int)gridDim.x) {}
        __threadfence();
    }
    __syncthreads();

    if (threadIdx.x < 32) {
        int base = 0;
        for (int j = threadIdx.x; j < (int)blockIdx.x; j += 32) base += g_bsum[j];
        #pragma unroll
        for (int o = 16; o >= 1; o >>= 1) base += __shfl_down_sync(0xFFFFFFFFu, base, o);
        if (threadIdx.x == 0) s_base = base;
    }
    __syncthreads();

    if (gi < N) g_start[gi] = s_base + incl - v;
    if (threadIdx.x == 0) {
        int done = atomicAdd(&g_ctr2, 1);
        if (done == (int)gridDim.x - 1) { g_ctr = 0; g_ctr2 = 0; }
    }
}

// K_fill: atomic-free — pos = start[dst] + precomputed rank
__global__ __launch_bounds__(256) void k_fill(const int* __restrict__ ei, int E) {
    int e = blockIdx.x * 256 + threadIdx.x;
    if (e >= E) return;
    int src = ei[e];
    int dst = ei[E + e];
    g_srcs[g_start[dst] + g_epos[e]] = src;
}

// ---------------------------------------------------------------------------
// Shared MMA macro
// ---------------------------------------------------------------------------
#define MMA_F16(c, a0, a1, a2, a3, b0, b1)                                    \
    asm volatile(                                                             \
        "mma.sync.aligned.m16n8k16.row.col.f32.f16.f16.f32 "                  \
        "{%0,%1,%2,%3}, {%4,%5,%6,%7}, {%8,%9}, {%0,%1,%2,%3};"               \
        : "+f"(c[0]), "+f"(c[1]), "+f"(c[2]), "+f"(c[3])                      \
        : "r"(a0), "r"(a1), "r"(a2), "r"(a3), "r"(b0), "r"(b1))

// ---------------------------------------------------------------------------
// K_agg_gemm1: FUSED aggregation + gemm1.
// Phase 1: each block aggregates its own 64 rows ((1+eps)*x + fp16 neighbor
//          sum, depth-2 HADD2 tree — bit-identical to the standalone k_agg)
//          and writes fp16 results DIRECTLY into the Xs staging smem.
// Phase 2: HMMA gemm (verified R12/R15 layout), out = t1h fp16 + stats1.
// ---------------------------------------------------------------------------
__global__ __launch_bounds__(256) void k_agg_gemm1(
    const float* __restrict__ x, const float* __restrict__ epsp,
    const unsigned* __restrict__ Wh,
    const float* __restrict__ b, unsigned* __restrict__ outH,
    float* __restrict__ statsOut, int N)
{
    __shared__ unsigned Xs[64 * 68];
    __shared__ unsigned Wsm[32 * 72];
    __shared__ float Bs[64];
    __shared__ float redS[8][32], redQ[8][32];

    const int tid = threadIdx.x;
    const int row0 = blockIdx.x * 64;

    if (tid < 64) Bs[tid] = b[tid];

    // Stage W (pre-converted fp16, uint4 copy)
    #pragma unroll
    for (int it = 0; it < 2; it++) {
        int idx = tid + it * 256;
        int k2 = idx >> 4, nq = idx & 15;
        uint4 u = ((const uint4*)Wh)[k2 * 16 + nq];
        *(uint4*)&Wsm[k2 * 72 + nq * 4] = u;
    }

    // Phase 1: aggregation for this block's 64 rows (2 passes x 32 rows,
    // 8 threads/row, q = 16-byte chunk).
    const float s = 1.0f + epsp[0];
    const uint4* xh4 = (const uint4*)g_xh;
    #pragma unroll
    for (int p = 0; p < 2; p++) {
        int rowL = p * 32 + (tid >> 3);
        int i = row0 + rowL;
        int q = tid & 7;
        uint4 o = make_uint4(0u, 0u, 0u, 0u);
        if (i < N) {
            float4 x0 = ((const float4*)x)[(size_t)i * 16 + q * 2];
            float4 x1 = ((const float4*)x)[(size_t)i * 16 + q * 2 + 1];
            float4 acc0 = make_float4(x0.x * s, x0.y * s, x0.z * s, x0.w * s);
            float4 acc1 = make_float4(x1.x * s, x1.y * s, x1.z * s, x1.w * s);
            int j = g_start[i];
            int je = g_start[i + 1];
            for (; j + 4 <= je; j += 4) {
                int s0 = g_srcs[j],     s1 = g_srcs[j + 1];
                int s2 = g_srcs[j + 2], s3 = g_srcs[j + 3];
                uint4 u0 = xh4[(size_t)s0 * 8 + q];
                uint4 u1 = xh4[(size_t)s1 * 8 + q];
                uint4 u2 = xh4[(size_t)s2 * 8 + q];
                uint4 u3 = xh4[(size_t)s3 * 8 + q];
                __half2 a0 = __hadd2(*(__half2*)&u0.x, *(__half2*)&u1.x);
                __half2 a1 = __hadd2(*(__half2*)&u0.y, *(__half2*)&u1.y);
                __half2 a2 = __hadd2(*(__half2*)&u0.z, *(__half2*)&u1.z);
                __half2 a3 = __hadd2(*(__half2*)&u0.w, *(__half2*)&u1.w);
                __half2 b0 = __hadd2(*(__half2*)&u2.x, *(__half2*)&u3.x);
                __half2 b1 = __hadd2(*(__half2*)&u2.y, *(__half2*)&u3.y);
                __half2 b2 = __hadd2(*(__half2*)&u2.z, *(__half2*)&u3.z);
                __half2 b3 = __hadd2(*(__half2*)&u2.w, *(__half2*)&u3.w);
                __half2 p0 = __hadd2(a0, b0);
                __half2 p1 = __hadd2(a1, b1);
                __half2 p2 = __hadd2(a2, b2);
                __half2 p3 = __hadd2(a3, b3);
                float2 f0 = __half22float2(p0);
                float2 f1 = __half22float2(p1);
                float2 f2 = __half22float2(p2);
                float2 f3 = __half22float2(p3);
                acc0.x += f0.x; acc0.y += f0.y; acc0.z += f1.x; acc0.w += f1.y;
                acc1.x += f2.x; acc1.y += f2.y; acc1.z += f3.x; acc1.w += f3.y;
            }
            if (j + 2 <= je) {
                int s0 = g_srcs[j], s1 = g_srcs[j + 1];
                uint4 u0 = xh4[(size_t)s0 * 8 + q];
                uint4 u1 = xh4[(size_t)s1 * 8 + q];
                __half2 p0 = __hadd2(*(__half2*)&u0.x, *(__half2*)&u1.x);
                __half2 p1 = __hadd2(*(__half2*)&u0.y, *(__half2*)&u1.y);
                __half2 p2 = __hadd2(*(__half2*)&u0.z, *(__half2*)&u1.z);
                __half2 p3 = __hadd2(*(__half2*)&u0.w, *(__half2*)&u1.w);
                float2 f0 = __half22float2(p0);
                float2 f1 = __half22float2(p1);
                float2 f2 = __half22float2(p2);
                float2 f3 = __half22float2(p3);
                acc0.x += f0.x; acc0.y += f0.y; acc0.z += f1.x; acc0.w += f1.y;
                acc1.x += f2.x; acc1.y += f2.y; acc1.z += f3.x; acc1.w += f3.y;
                j += 2;
            }
            if (j < je) {
                uint4 u = xh4[(size_t)g_srcs[j] * 8 + q];
                float2 f0 = __half22float2(*(__half2*)&u.x);
                float2 f1 = __half22float2(*(__half2*)&u.y);
                float2 f2 = __half22float2(*(__half2*)&u.z);
                float2 f3 = __half22float2(*(__half2*)&u.w);
                acc0.x += f0.x; acc0.y += f0.y; acc0.z += f1.x; acc0.w += f1.y;
                acc1.x += f2.x; acc1.y += f2.y; acc1.z += f3.x; acc1.w += f3.y;
            }
            __half2 h0 = __floats2half2_rn(acc0.x, acc0.y);
            __half2 h1 = __floats2half2_rn(acc0.z, acc0.w);
            __half2 h2 = __floats2half2_rn(acc1.x, acc1.y);
            __half2 h3 = __floats2half2_rn(acc1.z, acc1.w);
            o.x = *(unsigned*)&h0; o.y = *(unsigned*)&h1;
            o.z = *(unsigned*)&h2; o.w = *(unsigned*)&h3;
        }
        *(uint4*)&Xs[rowL * 68 + q * 4] = o;   // direct smem staging
    }
    __syncthreads();

    // Phase 2: HMMA gemm + stats (verified layout)
    const int w = tid >> 5, lane = tid & 31;
    const int ms = w & 3, nh = w >> 2;
    const int g = lane >> 2, t4 = lane & 3;
    const int mbase = ms * 16;
    const int nbase = nh * 32;

    float c_[4][4];
    #pragma unroll
    for (int nt = 0; nt < 4; nt++) {
        int col0 = nbase + nt * 8 + 2 * t4;
        c_[nt][0] = Bs[col0]; c_[nt][1] = Bs[col0 + 1];
        c_[nt][2] = Bs[col0]; c_[nt][3] = Bs[col0 + 1];
    }

    #pragma unroll
    for (int kk = 0; kk < 4; kk++) {
        int kb = kk * 8;
        unsigned A0 = Xs[(mbase + g) * 68 + kb + t4];
        unsigned A1 = Xs[(mbase + g + 8) * 68 + kb + t4];
        unsigned A2 = Xs[(mbase + g) * 68 + kb + t4 + 4];
        unsigned A3 = Xs[(mbase + g + 8) * 68 + kb + t4 + 4];
        #pragma unroll
        for (int nt = 0; nt < 4; nt++) {
            int n = nbase + nt * 8 + g;
            unsigned B0 = Wsm[(kb + t4) * 72 + n];
            unsigned B1 = Wsm[(kb + t4 + 4) * 72 + n];
            MMA_F16(c_[nt], A0, A1, A2, A3, B0, B1);
        }
    }

    int rg0 = row0 + mbase + g;
    int rg8 = rg0 + 8;
    #pragma unroll
    for (int nt = 0; nt < 4; nt++) {
        int col0 = nbase + nt * 8 + 2 * t4;
        float s0 = 0.f, s1 = 0.f, q0 = 0.f, q1 = 0.f;
        if (rg0 < N) {
            __half2 h = __floats2half2_rn(c_[nt][0], c_[nt][1]);
            outH[(size_t)rg0 * 32 + (col0 >> 1)] = *(unsigned*)&h;
            s0 += c_[nt][0]; s1 += c_[nt][1];
            q0 += c_[nt][0] * c_[nt][0]; q1 += c_[nt][1] * c_[nt][1];
        }
        if (rg8 < N) {
            __half2 h = __floats2half2_rn(c_[nt][2], c_[nt][3]);
            outH[(size_t)rg8 * 32 + (col0 >> 1)] = *(unsigned*)&h;
            s0 += c_[nt][2]; s1 += c_[nt][3];
            q0 += c_[nt][2] * c_[nt][2]; q1 += c_[nt][3] * c_[nt][3];
        }
        #pragma unroll
        for (int o = 16; o >= 4; o >>= 1) {
            s0 += __shfl_down_sync(0xFFFFFFFFu, s0, o);
            s1 += __shfl_down_sync(0xFFFFFFFFu, s1, o);
            q0 += __shfl_down_sync(0xFFFFFFFFu, q0, o);
            q1 += __shfl_down_sync(0xFFFFFFFFu, q1, o);
        }
        if (lane < 4) {
            redS[w][nt * 8 + 2 * t4] = s0;
            redS[w][nt * 8 + 2 * t4 + 1] = s1;
            redQ[w][nt * 8 + 2 * t4] = q0;
            redQ[w][nt * 8 + 2 * t4 + 1] = q1;
        }
    }
    __syncthreads();
    if (tid < 64) {
        int hh = tid >> 5, lc = tid & 31;
        float sv = redS[hh * 4 + 0][lc] + redS[hh * 4 + 1][lc]
                 + redS[hh * 4 + 2][lc] + redS[hh * 4 + 3][lc];
        float qv = redQ[hh * 4 + 0][lc] + redQ[hh * 4 + 1][lc]
                 + redQ[hh * 4 + 2][lc] + redQ[hh * 4 + 3][lc];
        atomicAdd(&statsOut[tid], sv);
        atomicAdd(&statsOut[64 + tid], qv);
    }
}

// ---------------------------------------------------------------------------
// K_gemm2: fp16 HMMA, in = t1h with fp16 BN1+ReLU staging, out fp32 + stats2
// (verified R15 mode-1 path)
// ---------------------------------------------------------------------------
__global__ __launch_bounds__(256) void k_gemm2(
    const uint4* __restrict__ inH,
    const unsigned* __restrict__ Wh,
    const float* __restrict__ b,
    float* __restrict__ outF,
    float* __restrict__ statsOut,
    const float* __restrict__ statsIn,
    const float* __restrict__ gamma, const float* __restrict__ beta,
    int N)
{
    __shared__ unsigned Xs[64 * 68];
    __shared__ unsigned Wsm[32 * 72];
    __shared__ float Bs[64], SC[64], SH[64];
    __shared__ unsigned SCH[32], SHH[32];
    __shared__ float redS[8][32], redQ[8][32];

    const int tid = threadIdx.x;
    const int row0 = blockIdx.x * 64;

    if (tid < 64) {
        Bs[tid] = b[tid];
        float invN = 1.0f / (float)N;
        float mean = statsIn[tid] * invN;
        float var  = statsIn[64 + tid] * invN - mean * mean;
        float sc = gamma[tid] * rsqrtf(var + 1e-5f);
        SC[tid] = sc;
        SH[tid] = beta[tid] - mean * sc;
    }
    __syncthreads();
    if (tid < 32) {
        __half2 hsc = __floats2half2_rn(SC[2 * tid], SC[2 * tid + 1]);
        __half2 hsh = __floats2half2_rn(SH[2 * tid], SH[2 * tid + 1]);
        SCH[tid] = *(unsigned*)&hsc;
        SHH[tid] = *(unsigned*)&hsh;
    }
    __syncthreads();

    #pragma unroll
    for (int it = 0; it < 2; it++) {
        int idx = tid + it * 256;
        int k2 = idx >> 4, nq = idx & 15;
        uint4 u = ((const uint4*)Wh)[k2 * 16 + nq];
        *(uint4*)&Wsm[k2 * 72 + nq * 4] = u;
    }
    const __half2 hzero = __floats2half2_rn(0.f, 0.f);
    #pragma unroll
    for (int it = 0; it < 2; it++) {
        int idx = tid + it * 256;
        int row = idx >> 3, w4 = idx & 7;
        int gr = row0 + row;
        uint4 u = make_uint4(0u, 0u, 0u, 0u);
        if (gr < N) u = inH[(size_t)gr * 8 + w4];
        int cp = w4 * 4;
        __half2 r0 = __hmax2(__hfma2(*(__half2*)&u.x, *(__half2*)&SCH[cp + 0], *(__half2*)&SHH[cp + 0]), hzero);
        __half2 r1 = __hmax2(__hfma2(*(__half2*)&u.y, *(__half2*)&SCH[cp + 1], *(__half2*)&SHH[cp + 1]), hzero);
        __half2 r2 = __hmax2(__hfma2(*(__half2*)&u.z, *(__half2*)&SCH[cp + 2], *(__half2*)&SHH[cp + 2]), hzero);
        __half2 r3 = __hmax2(__hfma2(*(__half2*)&u.w, *(__half2*)&SCH[cp + 3], *(__half2*)&SHH[cp + 3]), hzero);
        u.x = *(unsigned*)&r0; u.y = *(unsigned*)&r1;
        u.z = *(unsigned*)&r2; u.w = *(unsigned*)&r3;
        *(uint4*)&Xs[row * 68 + w4 * 4] = u;
    }
    __syncthreads();

    const int w = tid >> 5, lane = tid & 31;
    const int ms = w & 3, nh = w >> 2;
    const int g = lane >> 2, t4 = lane & 3;
    const int mbase = ms * 16;
    const int nbase = nh * 32;

    float c_[4][4];
    #pragma unroll
    for (int nt = 0; nt < 4; nt++) {
        int col0 = nbase + nt * 8 + 2 * t4;
        c_[nt][0] = Bs[col0]; c_[nt][1] = Bs[col0 + 1];
        c_[nt][2] = Bs[col0]; c_[nt][3] = Bs[col0 + 1];
    }

    #pragma unroll
    for (int kk = 0; kk < 4; kk++) {
        int kb = kk * 8;
        unsigned A0 = Xs[(mbase + g) * 68 + kb + t4];
        unsigned A1 = Xs[(mbase + g + 8) * 68 + kb + t4];
        unsigned A2 = Xs[(mbase + g) * 68 + kb + t4 + 4];
        unsigned A3 = Xs[(mbase + g + 8) * 68 + kb + t4 + 4];
        #pragma unroll
        for (int nt = 0; nt < 4; nt++) {
            int n = nbase + nt * 8 + g;
            unsigned B0 = Wsm[(kb + t4) * 72 + n];
            unsigned B1 = Wsm[(kb + t4 + 4) * 72 + n];
            MMA_F16(c_[nt], A0, A1, A2, A3, B0, B1);
        }
    }

    int rg0 = row0 + mbase + g;
    int rg8 = rg0 + 8;
    #pragma unroll
    for (int nt = 0; nt < 4; nt++) {
        int col0 = nbase + nt * 8 + 2 * t4;
        float s0 = 0.f, s1 = 0.f, q0 = 0.f, q1 = 0.f;
        if (rg0 < N) {
            *(float2*)&outF[(size_t)rg0 * 64 + col0] = make_float2(c_[nt][0], c_[nt][1]);
            s0 += c_[nt][0]; s1 += c_[nt][1];
            q0 += c_[nt][0] * c_[nt][0]; q1 += c_[nt][1] * c_[nt][1];
        }
        if (rg8 < N) {
            *(float2*)&outF[(size_t)rg8 * 64 + col0] = make_float2(c_[nt][2], c_[nt][3]);
            s0 += c_[nt][2]; s1 += c_[nt][3];
            q0 += c_[nt][2] * c_[nt][2]; q1 += c_[nt][3] * c_[nt][3];
        }
        #pragma unroll
        for (int o = 16; o >= 4; o >>= 1) {
            s0 += __shfl_down_sync(0xFFFFFFFFu, s0, o);
            s1 += __shfl_down_sync(0xFFFFFFFFu, s1, o);
            q0 += __shfl_down_sync(0xFFFFFFFFu, q0, o);
            q1 += __shfl_down_sync(0xFFFFFFFFu, q1, o);
        }
        if (lane < 4) {
            redS[w][nt * 8 + 2 * t4] = s0;
            redS[w][nt * 8 + 2 * t4 + 1] = s1;
            redQ[w][nt * 8 + 2 * t4] = q0;
            redQ[w][nt * 8 + 2 * t4 + 1] = q1;
        }
    }
    __syncthreads();
    if (tid < 64) {
        int hh = tid >> 5, lc = tid & 31;
        float sv = redS[hh * 4 + 0][lc] + redS[hh * 4 + 1][lc]
                 + redS[hh * 4 + 2][lc] + redS[hh * 4 + 3][lc];
        float qv = redQ[hh * 4 + 0][lc] + redQ[hh * 4 + 1][lc]
                 + redQ[hh * 4 + 2][lc] + redQ[hh * 4 + 3][lc];
        atomicAdd(&statsOut[tid], sv);
        atomicAdd(&statsOut[64 + tid], qv);
    }
}

// ---------------------------------------------------------------------------
// K_final: out = x + relu(BN(t2))
// ---------------------------------------------------------------------------
__global__ __launch_bounds__(256) void k_final(const float* __restrict__ x,
                                               const float* __restrict__ t2,
                                               const float* __restrict__ statsIn,
                                               const float* __restrict__ gamma,
                                               const float* __restrict__ beta,
                                               float* __restrict__ out, int N) {
    __shared__ float SC[64];
    __shared__ float SH[64];
    int tid = threadIdx.x;
    if (tid < 64) {
        float invN = 1.0f / (float)N;
        float mean = statsIn[tid] * invN;
        float var  = statsIn[64 + tid] * invN - mean * mean;
        float sc = gamma[tid] * rsqrtf(var + 1e-5f);
        SC[tid] = sc;
        SH[tid] = beta[tid] - mean * sc;
    }
    __syncthreads();
    int n4 = N * 16;
    for (int i = blockIdx.x * 256 + tid; i < n4; i += gridDim.x * 256) {
        int c = (i & 15) * 4;
        float4 v = ((const float4*)t2)[i];
        float4 xv = ((const float4*)x)[i];
        float4 o;
        o.x = xv.x + fmaxf(fmaf(v.x, SC[c + 0], SH[c + 0]), 0.f);
        o.y = xv.y + fmaxf(fmaf(v.y, SC[c + 1], SH[c + 1]), 0.f);
        o.z = xv.z + fmaxf(fmaf(v.z, SC[c + 2], SH[c + 2]), 0.f);
        o.w = xv.w + fmaxf(fmaf(v.w, SC[c + 3], SH[c + 3]), 0.f);
        ((float4*)out)[i] = o;
    }
}

// ---------------------------------------------------------------------------
extern "C" void kernel_launch(void* const* d_in, const int* in_sizes, int n_in,
                              void* d_out, int out_size) {
    const float* x    = (const float*)d_in[0];
    const int*   ei   = (const int*)d_in[1];
    const float* eps  = (const float*)d_in[2];
    const float* W1   = (const float*)d_in[3];
    const float* b1   = (const float*)d_in[4];
    const float* g1   = (const float*)d_in[5];
    const float* beta1= (const float*)d_in[6];
    const float* W2   = (const float*)d_in[7];
    const float* b2   = (const float*)d_in[8];
    const float* gh   = (const float*)d_in[9];
    const float* betah= (const float*)d_in[10];
    float* out = (float*)d_out;

    int N = in_sizes[0] / D;
    int E = in_sizes[1] / 2;
    if (N > MAXN) N = MAXN;
    if (E > MAXE) E = MAXE;

    float* agg;      cudaGetSymbolAddress((void**)&agg, g_agg);
    float* stats;    cudaGetSymbolAddress((void**)&stats, g_stats);
    uint4* t1h;      cudaGetSymbolAddress((void**)&t1h, g_t1h);
    unsigned* w1h;   cudaGetSymbolAddress((void**)&w1h, g_w1h);
    unsigned* w2h;   cudaGetSymbolAddress((void**)&w2h, g_w2h);

    int prepThreads = (N * 16 > E) ? N * 16 : E;
    int nScanBlocks = (N + SCAN_BLK - 1) / SCAN_BLK;

    k_prep<<<(prepThreads + 255) / 256, 256>>>(x, ei, W1, W2, N, E);
    k_scan<<<nScanBlocks, SCAN_BLK>>>(N);
    k_fill<<<(E + 255) / 256, 256>>>(ei, E);

    int gemmBlocks = (N + 63) / 64;
    // FUSED: aggregation + gemm1 -> t1h (fp16) + stats1
    k_agg_gemm1<<<gemmBlocks, 256>>>(x, eps, w1h, b1, (unsigned*)t1h, stats, N);
    // gemm2: t1h with fp16 BN1+ReLU -> agg (fp32) + stats2
    k_gemm2<<<gemmBlocks, 256>>>(t1h, w2h, b2, agg, stats + 128,
                                 stats, g1, beta1, N);

    k_final<<<(N * 16 + 255) / 256, 256>>>(x, agg, stats + 128, gh, betah, out, N);
}

// round 17
// speedup vs baseline: 1.0197x; 1.0197x over previous
#include <cuda_runtime.h>
#include <cuda_fp16.h>
#include <cstdint>

#define D 64
#define MAXN 100000
#define MAXE 1600000
#define SCAN_BLK 1024

// Scratch (device globals — no allocation allowed)
__device__ float    g_stats[256];        // sum1, sq1, sum2, sq2
__device__ uint2    g_xh[MAXN * 16];     // x staged fp16 (gather source)
__device__ uint4    g_aggh[MAXN * 8];    // agg result, packed fp16 rows
__device__ uint4    g_t1h[MAXN * 8];     // t1 (gemm1 out), packed fp16
__device__ uint4    g_t2h[MAXN * 8];     // t2 (gemm2 out), packed fp16
__device__ unsigned g_w1h[32 * 64];      // W1 fp16 [k2][n] half2(k-pair)
__device__ unsigned g_w2h[32 * 64];      // W2 fp16 [k2][n]
__device__ int      g_cnt[MAXN + SCAN_BLK];
__device__ int      g_start[MAXN + 1];
__device__ int      g_epos[MAXE];        // per-edge within-dst rank
__device__ int      g_srcs[MAXE];
__device__ int      g_bsum[SCAN_BLK];
__device__ int      g_ctr, g_ctr2;

// ---------------------------------------------------------------------------
// K_prep: stage x fp16 + degree hist (record per-edge rank) + zero stats
//         + W1/W2 -> fp16 [k2][n]
// ---------------------------------------------------------------------------
__global__ __launch_bounds__(256) void k_prep(const float* __restrict__ x,
                                              const int* __restrict__ ei,
                                              const float* __restrict__ W1,
                                              const float* __restrict__ W2,
                                              int N, int E) {
    int i = blockIdx.x * 256 + threadIdx.x;
    if (i < 256) g_stats[i] = 0.f;
    if (i == 0) g_start[N] = E;
    if (i < 2048) {
        int k2 = i >> 6, n = i & 63;
        __half2 h = __floats2half2_rn(W1[(2 * k2) * 64 + n], W1[(2 * k2 + 1) * 64 + n]);
        g_w1h[k2 * 64 + n] = *(unsigned*)&h;
    } else if (i < 4096) {
        int j = i - 2048;
        int k2 = j >> 6, n = j & 63;
        __half2 h = __floats2half2_rn(W2[(2 * k2) * 64 + n], W2[(2 * k2 + 1) * 64 + n]);
        g_w2h[k2 * 64 + n] = *(unsigned*)&h;
    }
    if (i < E) g_epos[i] = atomicAdd(&g_cnt[ei[E + i]], 1);
    int n4 = N * 16;
    if (i >= n4) return;
    float4 v = ((const float4*)x)[i];
    __half2 h0 = __floats2half2_rn(v.x, v.y);
    __half2 h1 = __floats2half2_rn(v.z, v.w);
    uint2 u;
    u.x = *(unsigned*)&h0;
    u.y = *(unsigned*)&h1;
    g_xh[i] = u;
}

__device__ __forceinline__ int block_scan_1024(int v, int* warpsum, int* total) {
    int lane = threadIdx.x & 31, wid = threadIdx.x >> 5;
    int inc = v;
    #pragma unroll
    for (int o = 1; o < 32; o <<= 1) {
        int u = __shfl_up_sync(0xFFFFFFFFu, inc, o);
        if (lane >= o) inc += u;
    }
    if (lane == 31) warpsum[wid] = inc;
    __syncthreads();
    if (wid == 0) {
        int w = warpsum[lane];
        #pragma unroll
        for (int o = 1; o < 32; o <<= 1) {
            int u = __shfl_up_sync(0xFFFFFFFFu, w, o);
            if (lane >= o) w += u;
        }
        warpsum[lane] = w;
    }
    __syncthreads();
    int base = (wid > 0) ? warpsum[wid - 1] : 0;
    *total = warpsum[31];
    return inc + base;
}

// K_scan: single-kernel exclusive scan (resident grid, verified)
__global__ __launch_bounds__(SCAN_BLK) void k_scan(int N) {
    __shared__ int warpsum[32];
    __shared__ int s_base;
    int gi = blockIdx.x * SCAN_BLK + threadIdx.x;
    int v = (gi < N) ? g_cnt[gi] : 0;
    if (gi < N) g_cnt[gi] = 0;
    int total;
    int incl = block_scan_1024(v, warpsum, &total);

    if (threadIdx.x == 0) {
        g_bsum[blockIdx.x] = total;
        __threadfence();
        atomicAdd(&g_ctr, 1);
        while (atomicAdd(&g_ctr, 0) < (int)gridDim.x) {}
        __threadfence();
    }
    __syncthreads();

    if (threadIdx.x < 32) {
        int base = 0;
        for (int j = threadIdx.x; j < (int)blockIdx.x; j += 32) base += g_bsum[j];
        #pragma unroll
        for (int o = 16; o >= 1; o >>= 1) base += __shfl_down_sync(0xFFFFFFFFu, base, o);
        if (threadIdx.x == 0) s_base = base;
    }
    __syncthreads();

    if (gi < N) g_start[gi] = s_base + incl - v;
    if (threadIdx.x == 0) {
        int done = atomicAdd(&g_ctr2, 1);
        if (done == (int)gridDim.x - 1) { g_ctr = 0; g_ctr2 = 0; }
    }
}

// K_fill: atomic-free — pos = start[dst] + precomputed rank
__global__ __launch_bounds__(256) void k_fill(const int* __restrict__ ei, int E) {
    int e = blockIdx.x * 256 + threadIdx.x;
    if (e >= E) return;
    int src = ei[e];
    int dst = ei[E + e];
    g_srcs[g_start[dst] + g_epos[e]] = src;
}

// ---------------------------------------------------------------------------
// K_agg: (1+eps)*x[i](fp32) + fp16 neighbor sum via depth-2 HADD2 tree
// (R14/R15 verified version)
// ---------------------------------------------------------------------------
__global__ __launch_bounds__(256) void k_agg(const float* __restrict__ x,
                                             const float* __restrict__ epsp,
                                             int N) {
    int tid = threadIdx.x;
    int i = blockIdx.x * 32 + (tid >> 3);
    int q = tid & 7;
    if (i >= N) return;
    float s = 1.0f + epsp[0];
    float4 x0 = ((const float4*)x)[(size_t)i * 16 + q * 2];
    float4 x1 = ((const float4*)x)[(size_t)i * 16 + q * 2 + 1];
    float4 acc0 = make_float4(x0.x * s, x0.y * s, x0.z * s, x0.w * s);
    float4 acc1 = make_float4(x1.x * s, x1.y * s, x1.z * s, x1.w * s);
    int j = g_start[i];
    int je = g_start[i + 1];
    const uint4* xh4 = (const uint4*)g_xh;
    for (; j + 4 <= je; j += 4) {
        int s0 = g_srcs[j],     s1 = g_srcs[j + 1];
        int s2 = g_srcs[j + 2], s3 = g_srcs[j + 3];
        uint4 u0 = xh4[(size_t)s0 * 8 + q];
        uint4 u1 = xh4[(size_t)s1 * 8 + q];
        uint4 u2 = xh4[(size_t)s2 * 8 + q];
        uint4 u3 = xh4[(size_t)s3 * 8 + q];
        __half2 a0 = __hadd2(*(__half2*)&u0.x, *(__half2*)&u1.x);
        __half2 a1 = __hadd2(*(__half2*)&u0.y, *(__half2*)&u1.y);
        __half2 a2 = __hadd2(*(__half2*)&u0.z, *(__half2*)&u1.z);
        __half2 a3 = __hadd2(*(__half2*)&u0.w, *(__half2*)&u1.w);
        __half2 b0 = __hadd2(*(__half2*)&u2.x, *(__half2*)&u3.x);
        __half2 b1 = __hadd2(*(__half2*)&u2.y, *(__half2*)&u3.y);
        __half2 b2 = __hadd2(*(__half2*)&u2.z, *(__half2*)&u3.z);
        __half2 b3 = __hadd2(*(__half2*)&u2.w, *(__half2*)&u3.w);
        __half2 p0 = __hadd2(a0, b0);
        __half2 p1 = __hadd2(a1, b1);
        __half2 p2 = __hadd2(a2, b2);
        __half2 p3 = __hadd2(a3, b3);
        float2 f0 = __half22float2(p0);
        float2 f1 = __half22float2(p1);
        float2 f2 = __half22float2(p2);
        float2 f3 = __half22float2(p3);
        acc0.x += f0.x; acc0.y += f0.y; acc0.z += f1.x; acc0.w += f1.y;
        acc1.x += f2.x; acc1.y += f2.y; acc1.z += f3.x; acc1.w += f3.y;
    }
    if (j + 2 <= je) {
        int s0 = g_srcs[j], s1 = g_srcs[j + 1];
        uint4 u0 = xh4[(size_t)s0 * 8 + q];
        uint4 u1 = xh4[(size_t)s1 * 8 + q];
        __half2 p0 = __hadd2(*(__half2*)&u0.x, *(__half2*)&u1.x);
        __half2 p1 = __hadd2(*(__half2*)&u0.y, *(__half2*)&u1.y);
        __half2 p2 = __hadd2(*(__half2*)&u0.z, *(__half2*)&u1.z);
        __half2 p3 = __hadd2(*(__half2*)&u0.w, *(__half2*)&u1.w);
        float2 f0 = __half22float2(p0);
        float2 f1 = __half22float2(p1);
        float2 f2 = __half22float2(p2);
        float2 f3 = __half22float2(p3);
        acc0.x += f0.x; acc0.y += f0.y; acc0.z += f1.x; acc0.w += f1.y;
        acc1.x += f2.x; acc1.y += f2.y; acc1.z += f3.x; acc1.w += f3.y;
        j += 2;
    }
    if (j < je) {
        uint4 u = xh4[(size_t)g_srcs[j] * 8 + q];
        float2 f0 = __half22float2(*(__half2*)&u.x);
        float2 f1 = __half22float2(*(__half2*)&u.y);
        float2 f2 = __half22float2(*(__half2*)&u.z);
        float2 f3 = __half22float2(*(__half2*)&u.w);
        acc0.x += f0.x; acc0.y += f0.y; acc0.z += f1.x; acc0.w += f1.y;
        acc1.x += f2.x; acc1.y += f2.y; acc1.z += f3.x; acc1.w += f3.y;
    }
    __half2 h0 = __floats2half2_rn(acc0.x, acc0.y);
    __half2 h1 = __floats2half2_rn(acc0.z, acc0.w);
    __half2 h2 = __floats2half2_rn(acc1.x, acc1.y);
    __half2 h3 = __floats2half2_rn(acc1.z, acc1.w);
    uint4 o;
    o.x = *(unsigned*)&h0; o.y = *(unsigned*)&h1;
    o.z = *(unsigned*)&h2; o.w = *(unsigned*)&h3;
    g_aggh[(size_t)i * 8 + q] = o;
}

// ---------------------------------------------------------------------------
// fp16 HMMA GEMM + fused BN stats (R15 verified).
// mode 0: raw uint4 staging (no BN). mode 1: fp16 BN+ReLU staging.
// Output: packed fp16 rows (outH). Stats from exact fp32 accumulators.
// ---------------------------------------------------------------------------
#define MMA_F16(c, a0, a1, a2, a3, b0, b1)                                    \
    asm volatile(                                                             \
        "mma.sync.aligned.m16n8k16.row.col.f32.f16.f16.f32 "                  \
        "{%0,%1,%2,%3}, {%4,%5,%6,%7}, {%8,%9}, {%0,%1,%2,%3};"               \
        : "+f"(c[0]), "+f"(c[1]), "+f"(c[2]), "+f"(c[3])                      \
        : "r"(a0), "r"(a1), "r"(a2), "r"(a3), "r"(b0), "r"(b1))

__global__ __launch_bounds__(256) void k_gemm_hmma(
    const uint4* __restrict__ inH,
    const unsigned* __restrict__ Wh,
    const float* __restrict__ b,
    unsigned* __restrict__ outH,
    float* __restrict__ statsOut,
    const float* __restrict__ statsIn,
    const float* __restrict__ gamma, const float* __restrict__ beta,
    int N, int mode)
{
    __shared__ unsigned Xs[64 * 68];
    __shared__ unsigned Wsm[32 * 72];
    __shared__ float Bs[64], SC[64], SH[64];
    __shared__ unsigned SCH[32], SHH[32];
    __shared__ float redS[8][32], redQ[8][32];

    const int tid = threadIdx.x;
    const int row0 = blockIdx.x * 64;

    if (tid < 64) {
        Bs[tid] = b[tid];
        if (mode == 1) {
            float invN = 1.0f / (float)N;
            float mean = statsIn[tid] * invN;
            float var  = statsIn[64 + tid] * invN - mean * mean;
            float sc = gamma[tid] * rsqrtf(var + 1e-5f);
            SC[tid] = sc;
            SH[tid] = beta[tid] - mean * sc;
        }
    }
    __syncthreads();
    if (mode == 1 && tid < 32) {
        __half2 hsc = __floats2half2_rn(SC[2 * tid], SC[2 * tid + 1]);
        __half2 hsh = __floats2half2_rn(SH[2 * tid], SH[2 * tid + 1]);
        SCH[tid] = *(unsigned*)&hsc;
        SHH[tid] = *(unsigned*)&hsh;
    }
    __syncthreads();

    #pragma unroll
    for (int it = 0; it < 2; it++) {
        int idx = tid + it * 256;
        int k2 = idx >> 4, nq = idx & 15;
        uint4 u = ((const uint4*)Wh)[k2 * 16 + nq];
        *(uint4*)&Wsm[k2 * 72 + nq * 4] = u;
    }
    const __half2 hzero = __floats2half2_rn(0.f, 0.f);
    #pragma unroll
    for (int it = 0; it < 2; it++) {
        int idx = tid + it * 256;
        int row = idx >> 3, w4 = idx & 7;
        int gr = row0 + row;
        uint4 u = make_uint4(0u, 0u, 0u, 0u);
        if (gr < N) u = inH[(size_t)gr * 8 + w4];
        if (mode == 1) {
            int cp = w4 * 4;
            __half2 r0 = __hmax2(__hfma2(*(__half2*)&u.x, *(__half2*)&SCH[cp + 0], *(__half2*)&SHH[cp + 0]), hzero);
            __half2 r1 = __hmax2(__hfma2(*(__half2*)&u.y, *(__half2*)&SCH[cp + 1], *(__half2*)&SHH[cp + 1]), hzero);
            __half2 r2 = __hmax2(__hfma2(*(__half2*)&u.z, *(__half2*)&SCH[cp + 2], *(__half2*)&SHH[cp + 2]), hzero);
            __half2 r3 = __hmax2(__hfma2(*(__half2*)&u.w, *(__half2*)&SCH[cp + 3], *(__half2*)&SHH[cp + 3]), hzero);
            u.x = *(unsigned*)&r0; u.y = *(unsigned*)&r1;
            u.z = *(unsigned*)&r2; u.w = *(unsigned*)&r3;
        }
        *(uint4*)&Xs[row * 68 + w4 * 4] = u;
    }
    __syncthreads();

    const int w = tid >> 5, lane = tid & 31;
    const int ms = w & 3, nh = w >> 2;
    const int g = lane >> 2, t4 = lane & 3;
    const int mbase = ms * 16;
    const int nbase = nh * 32;

    float c_[4][4];
    #pragma unroll
    for (int nt = 0; nt < 4; nt++) {
        int col0 = nbase + nt * 8 + 2 * t4;
        c_[nt][0] = Bs[col0]; c_[nt][1] = Bs[col0 + 1];
        c_[nt][2] = Bs[col0]; c_[nt][3] = Bs[col0 + 1];
    }

    #pragma unroll
    for (int kk = 0; kk < 4; kk++) {
        int kb = kk * 8;
        unsigned A0 = Xs[(mbase + g) * 68 + kb + t4];
        unsigned A1 = Xs[(mbase + g + 8) * 68 + kb + t4];
        unsigned A2 = Xs[(mbase + g) * 68 + kb + t4 + 4];
        unsigned A3 = Xs[(mbase + g + 8) * 68 + kb + t4 + 4];
        #pragma unroll
        for (int nt = 0; nt < 4; nt++) {
            int n = nbase + nt * 8 + g;
            unsigned B0 = Wsm[(kb + t4) * 72 + n];
            unsigned B1 = Wsm[(kb + t4 + 4) * 72 + n];
            MMA_F16(c_[nt], A0, A1, A2, A3, B0, B1);
        }
    }

    int rg0 = row0 + mbase + g;
    int rg8 = rg0 + 8;
    #pragma unroll
    for (int nt = 0; nt < 4; nt++) {
        int col0 = nbase + nt * 8 + 2 * t4;
        float s0 = 0.f, s1 = 0.f, q0 = 0.f, q1 = 0.f;
        if (rg0 < N) {
            __half2 h = __floats2half2_rn(c_[nt][0], c_[nt][1]);
            outH[(size_t)rg0 * 32 + (col0 >> 1)] = *(unsigned*)&h;
            s0 += c_[nt][0]; s1 += c_[nt][1];
            q0 += c_[nt][0] * c_[nt][0]; q1 += c_[nt][1] * c_[nt][1];
        }
        if (rg8 < N) {
            __half2 h = __floats2half2_rn(c_[nt][2], c_[nt][3]);
            outH[(size_t)rg8 * 32 + (col0 >> 1)] = *(unsigned*)&h;
            s0 += c_[nt][2]; s1 += c_[nt][3];
            q0 += c_[nt][2] * c_[nt][2]; q1 += c_[nt][3] * c_[nt][3];
        }
        #pragma unroll
        for (int o = 16; o >= 4; o >>= 1) {
            s0 += __shfl_down_sync(0xFFFFFFFFu, s0, o);
            s1 += __shfl_down_sync(0xFFFFFFFFu, s1, o);
            q0 += __shfl_down_sync(0xFFFFFFFFu, q0, o);
            q1 += __shfl_down_sync(0xFFFFFFFFu, q1, o);
        }
        if (lane < 4) {
            redS[w][nt * 8 + 2 * t4] = s0;
            redS[w][nt * 8 + 2 * t4 + 1] = s1;
            redQ[w][nt * 8 + 2 * t4] = q0;
            redQ[w][nt * 8 + 2 * t4 + 1] = q1;
        }
    }
    __syncthreads();
    if (tid < 64) {
        int hh = tid >> 5, lc = tid & 31;
        float sv = redS[hh * 4 + 0][lc] + redS[hh * 4 + 1][lc]
                 + redS[hh * 4 + 2][lc] + redS[hh * 4 + 3][lc];
        float qv = redQ[hh * 4 + 0][lc] + redQ[hh * 4 + 1][lc]
                 + redQ[hh * 4 + 2][lc] + redQ[hh * 4 + 3][lc];
        atomicAdd(&statsOut[tid], sv);
        atomicAdd(&statsOut[64 + tid], qv);
    }
}

// ---------------------------------------------------------------------------
// K_final: out = x + relu(BN(t2)), t2 read as packed fp16 (uint4 = 8 cols)
// ---------------------------------------------------------------------------
__global__ __launch_bounds__(256) void k_final(const float* __restrict__ x,
                                               const uint4* __restrict__ t2h,
                                               const float* __restrict__ statsIn,
                                               const float* __restrict__ gamma,
                                               const float* __restrict__ beta,
                                               float* __restrict__ out, int N) {
    __shared__ float SC[64];
    __shared__ float SH[64];
    int tid = threadIdx.x;
    if (tid < 64) {
        float invN = 1.0f / (float)N;
        float mean = statsIn[tid] * invN;
        float var  = statsIn[64 + tid] * invN - mean * mean;
        float sc = gamma[tid] * rsqrtf(var + 1e-5f);
        SC[tid] = sc;
        SH[tid] = beta[tid] - mean * sc;
    }
    __syncthreads();
    int n8 = N * 8;
    for (int i = blockIdx.x * 256 + tid; i < n8; i += gridDim.x * 256) {
        int c = (i & 7) * 8;          // 8 columns per uint4
        uint4 u = t2h[i];
        float2 f0 = __half22float2(*(__half2*)&u.x);
        float2 f1 = __half22float2(*(__half2*)&u.y);
        float2 f2 = __half22float2(*(__half2*)&u.z);
        float2 f3 = __half22float2(*(__half2*)&u.w);
        float4 xa = ((const float4*)x)[i * 2];
        float4 xb = ((const float4*)x)[i * 2 + 1];
        float4 oa, ob;
        oa.x = xa.x + fmaxf(fmaf(f0.x, SC[c + 0], SH[c + 0]), 0.f);
        oa.y = xa.y + fmaxf(fmaf(f0.y, SC[c + 1], SH[c + 1]), 0.f);
        oa.z = xa.z + fmaxf(fmaf(f1.x, SC[c + 2], SH[c + 2]), 0.f);
        oa.w = xa.w + fmaxf(fmaf(f1.y, SC[c + 3], SH[c + 3]), 0.f);
        ob.x = xb.x + fmaxf(fmaf(f2.x, SC[c + 4], SH[c + 4]), 0.f);
        ob.y = xb.y + fmaxf(fmaf(f2.y, SC[c + 5], SH[c + 5]), 0.f);
        ob.z = xb.z + fmaxf(fmaf(f3.x, SC[c + 6], SH[c + 6]), 0.f);
        ob.w = xb.w + fmaxf(fmaf(f3.y, SC[c + 7], SH[c + 7]), 0.f);
        ((float4*)out)[i * 2] = oa;
        ((float4*)out)[i * 2 + 1] = ob;
    }
}

// ---------------------------------------------------------------------------
extern "C" void kernel_launch(void* const* d_in, const int* in_sizes, int n_in,
                              void* d_out, int out_size) {
    const float* x    = (const float*)d_in[0];
    const int*   ei   = (const int*)d_in[1];
    const float* eps  = (const float*)d_in[2];
    const float* W1   = (const float*)d_in[3];
    const float* b1   = (const float*)d_in[4];
    const float* g1   = (const float*)d_in[5];
    const float* beta1= (const float*)d_in[6];
    const float* W2   = (const float*)d_in[7];
    const float* b2   = (const float*)d_in[8];
    const float* gh   = (const float*)d_in[9];
    const float* betah= (const float*)d_in[10];
    float* out = (float*)d_out;

    int N = in_sizes[0] / D;
    int E = in_sizes[1] / 2;
    if (N > MAXN) N = MAXN;
    if (E > MAXE) E = MAXE;

    float* stats;    cudaGetSymbolAddress((void**)&stats, g_stats);
    uint4* aggh;     cudaGetSymbolAddress((void**)&aggh, g_aggh);
    uint4* t1h;      cudaGetSymbolAddress((void**)&t1h, g_t1h);
    uint4* t2h;      cudaGetSymbolAddress((void**)&t2h, g_t2h);
    unsigned* w1h;   cudaGetSymbolAddress((void**)&w1h, g_w1h);
    unsigned* w2h;   cudaGetSymbolAddress((void**)&w2h, g_w2h);

    int prepThreads = (N * 16 > E) ? N * 16 : E;
    int nScanBlocks = (N + SCAN_BLK - 1) / SCAN_BLK;

    k_prep<<<(prepThreads + 255) / 256, 256>>>(x, ei, W1, W2, N, E);
    k_scan<<<nScanBlocks, SCAN_BLK>>>(N);
    k_fill<<<(E + 255) / 256, 256>>>(ei, E);
    k_agg<<<(N + 31) / 32, 256>>>(x, eps, N);

    int gemmBlocks = (N + 63) / 64;
    // gemm1: aggh (raw fp16) -> t1h (fp16) + stats1
    k_gemm_hmma<<<gemmBlocks, 256>>>(aggh, w1h, b1, (unsigned*)t1h, stats,
                                     nullptr, nullptr, nullptr, N, 0);
    // gemm2: t1h with fp16 BN1+ReLU -> t2h (fp16) + stats2
    k_gemm_hmma<<<gemmBlocks, 256>>>(t1h, w2h, b2, (unsigned*)t2h, stats + 128,
                                     stats, g1, beta1, N, 1);

    k_final<<<(N * 8 + 255) / 256, 256>>>(x, t2h, stats + 128, gh, betah, out, N);
}